// round 15
// baseline (speedup 1.0000x reference)
#include <cuda_runtime.h>
#include <math.h>
#include <stdint.h>

// Problem constants
#define Bb 2
#define Ss 1024
#define Ee 1024
#define NEx 8
#define Hh 16
#define Dh 64
#define NTOK (Bb*Ss)     // 2048
#define EH (Ee/2)        // 512
#define KT64 64          // K/16 for K=1024
#define NEB (NEx*Bb)     // 16

// ---------------- scratch (device globals) ----------------
__device__ __align__(16) float g_h [NTOK*EH];
__device__ __align__(16) float g_gates[NEx*NTOK];
__device__ __align__(16) float g_xpack [NTOK*Ee];        // packed+rounded x
__device__ __align__(16) float g_wpack [4*NEx*Ee*Ee];    // packed weights
__device__ __align__(16) float g_k2 [NEx*NTOK*Ee*2];     // K as (hi,lo) float2
__device__ __align__(16) float g_v2 [NEx*NTOK*Ee*2];     // V as (hi,lo) float2
__device__ __align__(16) float g_qc [NEB*Ss*Ee];         // compact Q*(1/8), tf32-rounded
__device__ __align__(16) float g_opack [NEB*Ss*Ee];      // packed gated attn out
__device__ __align__(16) float g_oproj [NEB*Ss*Ee];      // compact O-projection
__device__ int g_idx[NEB*Ss];
__device__ int g_cnt[NEB];
__device__ int g_tok_slot[NTOK*2];
__device__ int g_tok_ns[NTOK];

// ---------------- helpers ----------------
__device__ __forceinline__ uint32_t smem_u32(const void* p) {
    uint32_t a;
    asm("{ .reg .u64 t; cvta.to.shared.u64 t, %1; cvt.u32.u64 %0, t; }" : "=r"(a) : "l"(p));
    return a;
}
__device__ __forceinline__ float tf32r(float x) {
    uint32_t u;
    asm("cvt.rna.tf32.f32 %0, %1;" : "=r"(u) : "f"(x));
    return __uint_as_float(u);
}
#define CP_COMMIT() asm volatile("cp.async.commit_group;" ::: "memory")
#define CP_WAIT(n)  asm volatile("cp.async.wait_group %0;" :: "n"(n) : "memory")
#define CPA16(dst, src) \
    asm volatile("cp.async.cg.shared.global [%0], [%1], 16;" :: "r"(dst), "l"(src))

__device__ __forceinline__ void mma8(float* c, const uint32_t* a, const uint32_t* b) {
    asm volatile(
        "mma.sync.aligned.m16n8k8.row.col.f32.tf32.tf32.f32 "
        "{%0,%1,%2,%3}, {%4,%5,%6,%7}, {%8,%9}, {%0,%1,%2,%3};"
        : "+f"(c[0]), "+f"(c[1]), "+f"(c[2]), "+f"(c[3])
        : "r"(a[0]), "r"(a[1]), "r"(a[2]), "r"(a[3]), "r"(b[0]), "r"(b[1]));
}

// ============================================================
// Packing (tf32 RN + k-permute col' = (k%4)*4 + k/4)
// ============================================================
__global__ __launch_bounds__(256)
void pack_w_kernel(const float* __restrict__ qw, const float* __restrict__ kw,
                   const float* __restrict__ vw, const float* __restrict__ ow,
                   float* __restrict__ dst)
{
    const int kt = blockIdx.x, rb = blockIdx.y, m = blockIdx.z;
    const int tensor = m >> 3, e = m & 7;
    const float* src = (tensor == 0) ? qw : (tensor == 1) ? kw : (tensor == 2) ? vw : ow;
    src += (size_t)e * Ee * Ee + (size_t)rb * 128 * Ee + kt * 16;
    float* d = dst + (((size_t)m * 8 + rb) * KT64 + kt) * 2048;
    for (int el = threadIdx.x; el < 2048; el += 256) {
        int r = el >> 4, kk = el & 15;
        int colp = (kk & 3) * 4 + (kk >> 2);
        d[r * 16 + colp] = tf32r(src[(size_t)r * Ee + kk]);
    }
}

__global__ __launch_bounds__(256)
void pack_x_kernel(const float* __restrict__ x, float* __restrict__ dst)
{
    const int kt = blockIdx.x, mb = blockIdx.y;
    const float* src = x + (size_t)mb * 128 * Ee + kt * 16;
    float* d = dst + ((size_t)mb * KT64 + kt) * 2048;
    for (int el = threadIdx.x; el < 2048; el += 256) {
        int r = el >> 4, kk = el & 15;
        int colp = (kk & 3) * 4 + (kk >> 2);
        d[r * 16 + colp] = tf32r(src[(size_t)r * Ee + kk]);
    }
}

// ============================================================
// Batched tf32 mma.sync GEMM on packed operands. 4-stage pipeline,
// single barrier per k-chunk. 128x128 CTA tile, 8 warps of 64x32.
// MODE 0: dense KV -> (hi,lo) float2 out. grid (8,16,16).
// MODE 1: Q compact, fused gather, scale*0.125, single tf32 out. grid (8,8,16).
// MODE 2: O compact; A = packed flash output, fp32 out. grid (8,8,16).
// ============================================================
template<int MODE>
__global__ __launch_bounds__(256, 2)
void mma_gemm(const float* __restrict__ Apack, const float* __restrict__ Wpack,
              const float* __restrict__ bias0, const float* __restrict__ bias1,
              float* __restrict__ C0, float* __restrict__ C1,
              const int* __restrict__ idxp, const int* __restrict__ cnt)
{
    extern __shared__ __align__(16) float sm[];
    __shared__ int rmap[128];
    const int mb = blockIdx.y, nb = blockIdx.x, z = blockIdx.z;
    const int tid = threadIdx.x, lane = tid & 31, wid = tid >> 5;

    const float* Abase = nullptr;
    const float* Bbase;
    const float* bias = nullptr;
    float* Cp;
    if (MODE == 0) {
        const int e = z & 7, sel = z >> 3;
        Abase = Apack + (size_t)mb * KT64 * 2048;
        Bbase = Wpack + ((size_t)((1 + sel) * 8 + e) * 8 + nb) * KT64 * 2048;
        bias = (sel ? bias1 : bias0) + (size_t)e * Ee;
        Cp = (sel ? C1 : C0) + (size_t)e * NTOK * Ee * 2;   // float2 dest
    } else {
        const int e = z >> 1;
        const int cntv = cnt[z];
        if (mb * 128 >= cntv) return;
        if (MODE == 1) {
            const int b = z & 1;
            if (tid < 128) {
                int i = mb * 128 + tid;
                if (i > cntv - 1) i = cntv - 1;
                rmap[tid] = b * Ss + idxp[(size_t)z * Ss + i];
            }
        } else {
            Abase = Apack + ((size_t)z * 8 + mb) * KT64 * 2048;
        }
        Bbase = Wpack + ((size_t)((MODE == 1 ? 0 : 3) * 8 + e) * 8 + nb) * KT64 * 2048;
        if (MODE == 1) bias = bias0 + (size_t)e * Ee;
        Cp = C0 + (size_t)z * Ss * Ee;
    }
    if (MODE == 1) __syncthreads();

    const int g = lane >> 2, tg = lane & 3;
    const int warp_m = (wid & 1) * 64, warp_n = (wid >> 1) * 32;
    const uint32_t sa = smem_u32(sm);

    float acc[4][4][4];
#pragma unroll
    for (int mt = 0; mt < 4; mt++)
#pragma unroll
        for (int nt = 0; nt < 4; nt++)
#pragma unroll
            for (int r = 0; r < 4; r++) acc[mt][nt][r] = 0.f;

    auto load_stage = [&](int st, int kt) {
        const uint32_t db = sa + (uint32_t)st * 16384u;
#pragma unroll
        for (int l = 0; l < 2; l++) {
            int c = tid + l * 256;
            const float* ga;
            if (MODE == 1) {
                int row = c >> 2, q = c & 3;
                int t = rmap[row];
                ga = Apack + ((size_t)(t >> 7) * KT64 + kt) * 2048 + (t & 127) * 16 + q * 4;
            } else {
                ga = Abase + (size_t)kt * 2048 + c * 4;
            }
            CPA16(db + c * 16, ga);
            CPA16(db + 8192 + c * 16, Bbase + (size_t)kt * 2048 + c * 4);
        }
        CP_COMMIT();
    };

    load_stage(0, 0);
    load_stage(1, 1);
    load_stage(2, 2);

    for (int kt = 0; kt < KT64; kt++) {
        CP_WAIT(2);            // group kt complete
        __syncthreads();       // also orders reuse of stage (kt+3)&3 below
        int lkt = kt + 3; if (lkt > KT64 - 1) lkt = KT64 - 1;
        load_stage((kt + 3) & 3, lkt);   // uniform prefetch (clamped)

        const uint4* As = (const uint4*)(sm + (kt & 3) * 4096);
        const uint4* Bs = As + 512;

        uint4 aL[4], aH[4], bb[4];
#pragma unroll
        for (int mt = 0; mt < 4; mt++) {
            const int r0 = warp_m + mt * 16 + g;
            aL[mt] = As[r0 * 4 + tg];
            aH[mt] = As[(r0 + 8) * 4 + tg];
        }
#pragma unroll
        for (int nt = 0; nt < 4; nt++)
            bb[nt] = Bs[(warp_n + nt * 8 + g) * 4 + tg];

#pragma unroll
        for (int mt = 0; mt < 4; mt++)
#pragma unroll
            for (int nt = 0; nt < 4; nt++) {
                uint32_t a[4] = {aL[mt].x, aH[mt].x, aL[mt].y, aH[mt].y};
                uint32_t b[2] = {bb[nt].x, bb[nt].y};
                mma8(acc[mt][nt], a, b);
            }
#pragma unroll
        for (int mt = 0; mt < 4; mt++)
#pragma unroll
            for (int nt = 0; nt < 4; nt++) {
                uint32_t a[4] = {aL[mt].z, aH[mt].z, aL[mt].w, aH[mt].w};
                uint32_t b[2] = {bb[nt].z, bb[nt].w};
                mma8(acc[mt][nt], a, b);
            }
    }

    // epilogue
    const int n0 = nb * 128;
#pragma unroll
    for (int mt = 0; mt < 4; mt++) {
#pragma unroll
        for (int h2 = 0; h2 < 2; h2++) {
            const int ti = mb * 128 + warp_m + mt * 16 + g + h2 * 8;
#pragma unroll
            for (int nt = 0; nt < 4; nt++) {
                const int col = warp_n + nt * 8 + 2 * tg;
                float v0 = acc[mt][nt][h2 * 2 + 0];
                float v1 = acc[mt][nt][h2 * 2 + 1];
                if (MODE != 2) {
                    v0 += bias[n0 + col];
                    v1 += bias[n0 + col + 1];
                }
                if (MODE == 0) {
                    float h0 = tf32r(v0), l0 = tf32r(v0 - h0);
                    float h1 = tf32r(v1), l1 = tf32r(v1 - h1);
                    float* crp = Cp + ((size_t)ti * Ee + n0 + col) * 2;
                    *(float4*)crp = make_float4(h0, l0, h1, l1);
                } else if (MODE == 1) {
                    float* crp = Cp + (size_t)ti * Ee + n0;
                    *(float2*)(crp + col) =
                        make_float2(tf32r(v0 * 0.125f), tf32r(v1 * 0.125f));
                } else {
                    float* crp = Cp + (size_t)ti * Ee + n0;
                    *(float2*)(crp + col) = make_float2(v0, v1);
                }
            }
        }
    }
}

// ============================================================
// fp32 SGEMM (router only): C = A @ B^T + bias
// ============================================================
__global__ __launch_bounds__(256)
void gemm_nt_kernel(const float* __restrict__ A, const float* __restrict__ Bm,
                    const float* __restrict__ bias, float* __restrict__ C,
                    int M, int N, int K)
{
    __shared__ __align__(16) float As[2][16][132];
    __shared__ __align__(16) float Bs[2][16][132];
    const int m0 = blockIdx.y * 128, n0 = blockIdx.x * 128;
    const int tid = threadIdx.x;
    const int tx = tid & 15, ty = tid >> 4;
    const int lrow = tid >> 2, lq = tid & 3;
    const float* Ab = A + (size_t)m0 * K + lq * 4;
    const float* Bb2 = Bm + (size_t)n0 * K + lq * 4;
    float acc[8][8];
#pragma unroll
    for (int i = 0; i < 8; i++)
#pragma unroll
        for (int j = 0; j < 8; j++) acc[i][j] = 0.f;
    const int KTl = K >> 4;
#pragma unroll
    for (int i = 0; i < 2; i++) {
        int row = lrow + i * 64;
        float4 va = *(const float4*)(Ab + (size_t)row * K);
        float4 vb = *(const float4*)(Bb2 + (size_t)row * K);
        As[0][lq*4+0][row] = va.x; As[0][lq*4+1][row] = va.y;
        As[0][lq*4+2][row] = va.z; As[0][lq*4+3][row] = va.w;
        Bs[0][lq*4+0][row] = vb.x; Bs[0][lq*4+1][row] = vb.y;
        Bs[0][lq*4+2][row] = vb.z; Bs[0][lq*4+3][row] = vb.w;
    }
    __syncthreads();
    for (int kt = 0; kt < KTl; kt++) {
        const int cb = kt & 1, nbuf = cb ^ 1;
        float4 pa[2], pb[2];
        if (kt + 1 < KTl) {
#pragma unroll
            for (int i = 0; i < 2; i++) {
                int row = lrow + i * 64;
                pa[i] = *(const float4*)(Ab + (size_t)row * K + (kt + 1) * 16);
                pb[i] = *(const float4*)(Bb2 + (size_t)row * K + (kt + 1) * 16);
            }
        }
#pragma unroll
        for (int kk = 0; kk < 16; kk++) {
            float a[8], bv[8];
            *(float4*)&a[0] = *(const float4*)&As[cb][kk][ty * 8];
            *(float4*)&a[4] = *(const float4*)&As[cb][kk][ty * 8 + 4];
            *(float4*)&bv[0] = *(const float4*)&Bs[cb][kk][tx * 8];
            *(float4*)&bv[4] = *(const float4*)&Bs[cb][kk][tx * 8 + 4];
#pragma unroll
            for (int i = 0; i < 8; i++)
#pragma unroll
                for (int j = 0; j < 8; j++)
                    acc[i][j] = fmaf(a[i], bv[j], acc[i][j]);
        }
        if (kt + 1 < KTl) {
#pragma unroll
            for (int i = 0; i < 2; i++) {
                int row = lrow + i * 64;
                As[nbuf][lq*4+0][row] = pa[i].x; As[nbuf][lq*4+1][row] = pa[i].y;
                As[nbuf][lq*4+2][row] = pa[i].z; As[nbuf][lq*4+3][row] = pa[i].w;
                Bs[nbuf][lq*4+0][row] = pb[i].x; Bs[nbuf][lq*4+1][row] = pb[i].y;
                Bs[nbuf][lq*4+2][row] = pb[i].z; Bs[nbuf][lq*4+3][row] = pb[i].w;
            }
        }
        __syncthreads();
    }
#pragma unroll
    for (int i = 0; i < 8; i++) {
        int m = m0 + ty * 8 + i;
        float* Crow = C + (size_t)m * N + n0 + tx * 8;
#pragma unroll
        for (int j = 0; j < 8; j++) {
            float v = acc[i][j];
            v += bias[n0 + tx * 8 + j];
            Crow[j] = v;
        }
    }
}

// ============================================================
// Fused LayerNorm + ReLU + router logits + softmax + top-2 gates.
// One block per token; h read once from global, never written back.
// ============================================================
__global__ __launch_bounds__(256)
void ln_router_kernel(const float* __restrict__ h, const float* __restrict__ g,
                      const float* __restrict__ b, const float* __restrict__ rW2,
                      const float* __restrict__ rb2, float* __restrict__ gates)
{
    const int t = blockIdx.x;
    __shared__ float hs[EH];
    __shared__ float red[16];
    __shared__ float sh_mean, sh_rstd;
    __shared__ float lg[NEx];
    const float* row = h + (size_t)t * EH;
    const int lane = threadIdx.x & 31, w = threadIdx.x >> 5;

    float s = 0.f, s2 = 0.f;
    for (int i = threadIdx.x; i < EH; i += 256) {
        float v = row[i];
        hs[i] = v;
        s += v;
        s2 = fmaf(v, v, s2);
    }
#pragma unroll
    for (int o = 16; o; o >>= 1) {
        s  += __shfl_xor_sync(0xffffffffu, s, o);
        s2 += __shfl_xor_sync(0xffffffffu, s2, o);
    }
    if (lane == 0) { red[w] = s; red[8 + w] = s2; }
    __syncthreads();
    if (threadIdx.x == 0) {
        float ts = 0.f, ts2 = 0.f;
        for (int i = 0; i < 8; i++) { ts += red[i]; ts2 += red[8 + i]; }
        float mean = ts * (1.f / EH);
        float var = ts2 * (1.f / EH) - mean * mean;
        sh_mean = mean;
        sh_rstd = rsqrtf(var + 1e-5f);
    }
    __syncthreads();
    const float mean = sh_mean, rstd = sh_rstd;
    for (int i = threadIdx.x; i < EH; i += 256) {
        float v = (hs[i] - mean) * rstd * g[i] + b[i];
        hs[i] = fmaxf(v, 0.f);
    }
    __syncthreads();

    // 8 warps -> 8 logits
    float sdot = 0.f;
    const float* wrow = rW2 + (size_t)w * EH;
    for (int i = lane; i < EH; i += 32) sdot = fmaf(hs[i], wrow[i], sdot);
#pragma unroll
    for (int o = 16; o; o >>= 1) sdot += __shfl_xor_sync(0xffffffffu, sdot, o);
    if (lane == 0) lg[w] = sdot + rb2[w];
    __syncthreads();
    if (threadIdx.x == 0) {
        float mx = lg[0];
        for (int e = 1; e < NEx; e++) mx = fmaxf(mx, lg[e]);
        float pe[NEx]; float sum = 0.f;
        for (int e = 0; e < NEx; e++) { pe[e] = expf(lg[e] - mx); sum += pe[e]; }
        float inv = 1.f / sum;
        for (int e = 0; e < NEx; e++) pe[e] *= inv;
        int i1 = 0;
        for (int e = 1; e < NEx; e++) if (pe[e] > pe[i1]) i1 = e;
        int i2 = (i1 == 0) ? 1 : 0;
        for (int e = 0; e < NEx; e++) {
            if (e == i1) continue;
            if (pe[e] > pe[i2]) i2 = e;
        }
        float tsum = pe[i1] + pe[i2];
        for (int e = 0; e < NEx; e++) gates[e * NTOK + t] = 0.f;
        gates[i1 * NTOK + t] = pe[i1] / tsum;
        gates[i2 * NTOK + t] = pe[i2] / tsum;
    }
}

// ============================================================
// lists + slots
// ============================================================
__global__ __launch_bounds__(256)
void zero_meta_kernel(int* __restrict__ cnt, int* __restrict__ tok_ns)
{
    const int i = blockIdx.x * 256 + threadIdx.x;
    if (i < NEB) cnt[i] = 0;
    if (i < NTOK) tok_ns[i] = 0;
}
__global__ __launch_bounds__(256)
void build_lists_kernel(const float* __restrict__ gates, int* __restrict__ idx,
                        int* __restrict__ cnt, int* __restrict__ tok_slot,
                        int* __restrict__ tok_ns)
{
    const int e = blockIdx.x;
    for (int t = threadIdx.x; t < NTOK; t += 256) {
        if (gates[e * NTOK + t] > 0.f) {
            int b = t >> 10, s = t & (Ss - 1);
            int pos = atomicAdd(&cnt[e * Bb + b], 1);
            idx[(e * Bb + b) * Ss + pos] = s;
            int sl = atomicAdd(&tok_ns[t], 1);
            if (sl < 2) tok_slot[t * 2 + sl] = (e * Bb + b) * Ss + pos;
        }
    }
}

// ============================================================
// Tensor-core flash attention on pre-split operands.
// QK^T: 2-term (q_hi x (k_hi + k_lo)); Q pre-scaled by 1/8, pre-rounded.
// PV: 2-term (p_hi x (v_hi + v_lo)). Epilogue writes packed opack.
// smem: K2[2][64][68] float2, V2[2][64][68] float2, Ps[128][68] float.
// ============================================================
__global__ __launch_bounds__(256)
void flash_attn_tensor(const float* __restrict__ Qf, const float* __restrict__ K2f,
                       const float* __restrict__ V2f, const float* __restrict__ gates,
                       const int* __restrict__ idx, const int* __restrict__ cnt,
                       float* __restrict__ Opack)
{
    extern __shared__ __align__(16) char smc[];
    float (*Ps)[68] = (float(*)[68])(smc + 139264);
    __shared__ float sgate[128];
    __shared__ int s_nact;

    const int bx = blockIdx.x;
    const int z = blockIdx.y >> 4, hh = blockIdx.y & 15;
    const int e = z >> 1, b = z & 1;
    const int tid = threadIdx.x, lane = tid & 31, wid = tid >> 5;
    const int g = lane >> 2, tg = lane & 3;
    const int row0 = wid * 16;

    if (tid == 0) s_nact = cnt[z];
    __syncthreads();
    const int n_act = s_nact;
    if (bx * 128 >= n_act) return;

    const float2* K2 = (const float2*)K2f;
    const float2* V2 = (const float2*)V2f;
    const size_t kbase2 = ((size_t)e * NTOK + (size_t)b * Ss) * Ee + (size_t)hh * Dh;
    const uint32_t sa = smem_u32(smc);

    auto load_kv = [&](int buf, int nt) {
        const float2* kg = K2 + kbase2 + (size_t)(nt * 64) * Ee;
        const float2* vg = V2 + kbase2 + (size_t)(nt * 64) * Ee;
        const uint32_t kb2 = sa + (uint32_t)buf * 34816u;
        const uint32_t vb2 = sa + 69632u + (uint32_t)buf * 34816u;
#pragma unroll
        for (int l = 0; l < 8; l++) {
            int i = tid + l * 256;
            int r = i >> 5, c = i & 31;
            CPA16(kb2 + r * 544 + c * 16, (const char*)(kg + (size_t)r * Ee) + c * 16);
            CPA16(vb2 + r * 544 + c * 16, (const char*)(vg + (size_t)r * Ee) + c * 16);
        }
        CP_COMMIT();
    };

    load_kv(0, 0);   // prefetch first tile ASAP

    if (tid < 128) {
        int i = bx * 128 + tid;
        sgate[tid] = (i < n_act)
            ? gates[e * NTOK + b * Ss + idx[(size_t)z * Ss + i]] : 1.f;
    }

    // Q fragments (hi only, pre-scaled/rounded) direct from global
    uint32_t qh[8][4];
    {
        const float* qp = Qf + ((size_t)z * Ss + bx * 128) * Ee + (size_t)hh * Dh;
#pragma unroll
        for (int kc = 0; kc < 8; kc++) {
#pragma unroll
            for (int j = 0; j < 4; j++) {
                const int qrow = row0 + g + (j & 1) * 8;
                const int col = kc * 8 + tg + (j >> 1) * 4;
                qh[kc][j] = __float_as_uint(qp[(size_t)qrow * Ee + col]);
            }
        }
    }

    float oacc[8][4];
#pragma unroll
    for (int d8 = 0; d8 < 8; d8++)
#pragma unroll
        for (int r = 0; r < 4; r++) oacc[d8][r] = 0.f;
    float m0 = -INFINITY, m1 = -INFINITY, l0 = 0.f, l1 = 0.f;

    for (int nt = 0; nt < Ss / 64; nt++) {
        const int buf = nt & 1;
        if (nt + 1 < Ss / 64) { load_kv(buf ^ 1, nt + 1); CP_WAIT(1); }
        else CP_WAIT(0);
        __syncthreads();

        float2 (*K2s)[68] = (float2(*)[68])(smc + buf * 34816);
        float2 (*V2s)[68] = (float2(*)[68])(smc + 69632 + buf * 34816);

        // ---- S = Q K^T (2-term) ----
        float sacc[8][4];
#pragma unroll
        for (int n8 = 0; n8 < 8; n8++)
#pragma unroll
            for (int r = 0; r < 4; r++) sacc[n8][r] = 0.f;

#pragma unroll
        for (int kc = 0; kc < 8; kc++) {
#pragma unroll
            for (int n8 = 0; n8 < 8; n8++) {
                float2 k0 = K2s[n8 * 8 + g][kc * 8 + tg];
                float2 k1 = K2s[n8 * 8 + g][kc * 8 + tg + 4];
                uint32_t kh2[2] = {__float_as_uint(k0.x), __float_as_uint(k1.x)};
                uint32_t kl2[2] = {__float_as_uint(k0.y), __float_as_uint(k1.y)};
                mma8(sacc[n8], qh[kc], kh2);
                mma8(sacc[n8], qh[kc], kl2);
            }
        }

        // ---- online softmax (fp32) ----
        float rmax0 = -INFINITY, rmax1 = -INFINITY;
#pragma unroll
        for (int n8 = 0; n8 < 8; n8++) {
            rmax0 = fmaxf(rmax0, fmaxf(sacc[n8][0], sacc[n8][1]));
            rmax1 = fmaxf(rmax1, fmaxf(sacc[n8][2], sacc[n8][3]));
        }
        rmax0 = fmaxf(rmax0, __shfl_xor_sync(0xffffffffu, rmax0, 1));
        rmax0 = fmaxf(rmax0, __shfl_xor_sync(0xffffffffu, rmax0, 2));
        rmax1 = fmaxf(rmax1, __shfl_xor_sync(0xffffffffu, rmax1, 1));
        rmax1 = fmaxf(rmax1, __shfl_xor_sync(0xffffffffu, rmax1, 2));
        float newm0 = fmaxf(m0, rmax0), newm1 = fmaxf(m1, rmax1);
        float corr0 = __expf(m0 - newm0), corr1 = __expf(m1 - newm1);
        float rs0 = 0.f, rs1 = 0.f;
#pragma unroll
        for (int n8 = 0; n8 < 8; n8++) {
            float p0 = __expf(sacc[n8][0] - newm0);
            float p1 = __expf(sacc[n8][1] - newm0);
            float p2 = __expf(sacc[n8][2] - newm1);
            float p3 = __expf(sacc[n8][3] - newm1);
            rs0 += p0 + p1; rs1 += p2 + p3;
            *(float2*)&Ps[row0 + g][n8 * 8 + 2 * tg] = make_float2(p0, p1);
            *(float2*)&Ps[row0 + g + 8][n8 * 8 + 2 * tg] = make_float2(p2, p3);
        }
        rs0 += __shfl_xor_sync(0xffffffffu, rs0, 1);
        rs0 += __shfl_xor_sync(0xffffffffu, rs0, 2);
        rs1 += __shfl_xor_sync(0xffffffffu, rs1, 1);
        rs1 += __shfl_xor_sync(0xffffffffu, rs1, 2);
        l0 = l0 * corr0 + rs0; m0 = newm0;
        l1 = l1 * corr1 + rs1; m1 = newm1;
#pragma unroll
        for (int d8 = 0; d8 < 8; d8++) {
            oacc[d8][0] *= corr0; oacc[d8][1] *= corr0;
            oacc[d8][2] *= corr1; oacc[d8][3] *= corr1;
        }
        __syncwarp();  // P rows are warp-private

        // ---- O += P V (2-term: P_hi x (V_hi + V_lo)) ----
#pragma unroll
        for (int kc = 0; kc < 8; kc++) {
            uint32_t ph[4];
#pragma unroll
            for (int j = 0; j < 4; j++) {
                float v = Ps[row0 + g + (j & 1) * 8][kc * 8 + tg + (j >> 1) * 4];
                ph[j] = __float_as_uint(tf32r(v));
            }
#pragma unroll
            for (int d8 = 0; d8 < 8; d8++) {
                float2 v0 = V2s[kc * 8 + tg][d8 * 8 + g];
                float2 v1 = V2s[kc * 8 + tg + 4][d8 * 8 + g];
                uint32_t vh2[2] = {__float_as_uint(v0.x), __float_as_uint(v1.x)};
                uint32_t vl2[2] = {__float_as_uint(v0.y), __float_as_uint(v1.y)};
                mma8(oacc[d8], ph, vh2);
                mma8(oacc[d8], ph, vl2);
            }
        }
        __syncthreads();  // this tile's buffers safe to refill next iter
    }

    // ---- epilogue: /l, *gate, write PACKED (fused pack_o) ----
    float* dbase = Opack + ((size_t)(z * 8 + bx) * KT64) * 2048;
#pragma unroll
    for (int half = 0; half < 2; half++) {
        const int rr = row0 + g + half * 8;
        const int rg = bx * 128 + rr;
        if (rg < n_act) {
            const float gv = sgate[rr] / (half ? l1 : l0);
            float* dp = dbase + rr * 16;
#pragma unroll
            for (int d8 = 0; d8 < 8; d8++) {
#pragma unroll
                for (int w2 = 0; w2 < 2; w2++) {
                    const int c = hh * 64 + d8 * 8 + 2 * tg + w2;
                    const int kt = c >> 4, kk = c & 15;
                    const int colp = (kk & 3) * 4 + (kk >> 2);
                    const float val = oacc[d8][half * 2 + w2] * gv;
                    dp[(size_t)kt * 2048 + colp] = tf32r(val);
                }
            }
        }
    }
}

// ============================================================
// combine: out = Sum_e gates*ob + Sum over token's <=2 compact rows
// ============================================================
__global__ __launch_bounds__(256)
void combine_kernel(const float* __restrict__ gates, const float* __restrict__ ob,
                    const float* __restrict__ oproj, const int* __restrict__ tok_slot,
                    const int* __restrict__ tok_ns, float* __restrict__ out)
{
    const int i = blockIdx.x * 256 + threadIdx.x;
    const int t = i >> 10;
    const int j = i & (Ee - 1);
    float s = 0.f;
#pragma unroll
    for (int e = 0; e < NEx; e++)
        s = fmaf(gates[e * NTOK + t], ob[e * Ee + j], s);
    const int ns = tok_ns[t];
    int s0 = tok_slot[t * 2], s1 = tok_slot[t * 2 + 1];
    if (ns >= 2) {
        if (s1 < s0) { int tmp = s0; s0 = s1; s1 = tmp; }
        s += oproj[(size_t)s0 * Ee + j];
        s += oproj[(size_t)s1 * Ee + j];
    } else if (ns == 1) {
        s += oproj[(size_t)s0 * Ee + j];
    }
    out[i] = s;
}

// ============================================================
// launch
// ============================================================
extern "C" void kernel_launch(void* const* d_in, const int* in_sizes, int n_in,
                              void* d_out, int out_size)
{
    const float* x    = (const float*)d_in[0];
    const float* rW1  = (const float*)d_in[1];
    const float* rb1  = (const float*)d_in[2];
    const float* ln_g = (const float*)d_in[3];
    const float* ln_b = (const float*)d_in[4];
    const float* rW2  = (const float*)d_in[5];
    const float* rb2  = (const float*)d_in[6];
    const float* qW   = (const float*)d_in[7];
    const float* qb   = (const float*)d_in[8];
    const float* kW   = (const float*)d_in[9];
    const float* kb   = (const float*)d_in[10];
    const float* vW   = (const float*)d_in[11];
    const float* vb   = (const float*)d_in[12];
    const float* oW   = (const float*)d_in[13];
    const float* ob   = (const float*)d_in[14];
    float* out = (float*)d_out;

    float *h, *gates, *xpack, *wpack, *k2, *v2, *qc, *opack, *oproj;
    int *idx, *cnt, *tok_slot, *tok_ns;
    cudaGetSymbolAddress((void**)&h, g_h);
    cudaGetSymbolAddress((void**)&gates, g_gates);
    cudaGetSymbolAddress((void**)&xpack, g_xpack);
    cudaGetSymbolAddress((void**)&wpack, g_wpack);
    cudaGetSymbolAddress((void**)&k2, g_k2);
    cudaGetSymbolAddress((void**)&v2, g_v2);
    cudaGetSymbolAddress((void**)&qc, g_qc);
    cudaGetSymbolAddress((void**)&opack, g_opack);
    cudaGetSymbolAddress((void**)&oproj, g_oproj);
    cudaGetSymbolAddress((void**)&idx, g_idx);
    cudaGetSymbolAddress((void**)&cnt, g_cnt);
    cudaGetSymbolAddress((void**)&tok_slot, g_tok_slot);
    cudaGetSymbolAddress((void**)&tok_ns, g_tok_ns);

    constexpr int FLASH_SMEM = 4 * 34816 + 128 * 68 * 4;   // 174,080 B
    constexpr int GEMM_SMEM = 4 * 16384;                   // 65,536 B
    cudaFuncSetAttribute(flash_attn_tensor,
                         cudaFuncAttributeMaxDynamicSharedMemorySize, FLASH_SMEM);
    cudaFuncSetAttribute(mma_gemm<0>,
                         cudaFuncAttributeMaxDynamicSharedMemorySize, GEMM_SMEM);
    cudaFuncSetAttribute(mma_gemm<1>,
                         cudaFuncAttributeMaxDynamicSharedMemorySize, GEMM_SMEM);
    cudaFuncSetAttribute(mma_gemm<2>,
                         cudaFuncAttributeMaxDynamicSharedMemorySize, GEMM_SMEM);

    const dim3 blk(256);

    // 1-2: pack weights and x
    pack_w_kernel<<<dim3(64, 8, 32), blk>>>(qW, kW, vW, oW, wpack);
    pack_x_kernel<<<dim3(64, 16), blk>>>(x, xpack);
    // 3: router hidden (fp32)
    gemm_nt_kernel<<<dim3(EH / 128, NTOK / 128), blk>>>(x, rW1, rb1, h, NTOK, EH, Ee);
    // 4: K+V projections, all experts, (hi,lo) output (PROFILED LAUNCH)
    mma_gemm<0><<<dim3(8, 16, 16), blk, GEMM_SMEM>>>(
        xpack, wpack, kb, vb, k2, v2, nullptr, nullptr);
    // 5-7: fused LN+router, lists
    ln_router_kernel<<<NTOK, blk>>>(h, ln_g, ln_b, rW2, rb2, gates);
    zero_meta_kernel<<<NTOK / 256, blk>>>(cnt, tok_ns);
    build_lists_kernel<<<NEx, blk>>>(gates, idx, cnt, tok_slot, tok_ns);
    // 8: Q projections, fused gather, scaled single-tf32 output
    mma_gemm<1><<<dim3(8, 8, NEB), blk, GEMM_SMEM>>>(
        xpack, wpack, qb, nullptr, qc, nullptr, idx, cnt);
    // 9: flash attention (2-term QK / 2-term PV, writes packed O)
    flash_attn_tensor<<<dim3(8, NEB * Hh), blk, FLASH_SMEM>>>(
        qc, k2, v2, gates, idx, cnt, opack);
    // 10: O projections on packed flash output
    mma_gemm<2><<<dim3(8, 8, NEB), blk, GEMM_SMEM>>>(
        opack, wpack, nullptr, nullptr, oproj, nullptr, nullptr, cnt);
    // 11: combine
    combine_kernel<<<(NTOK * Ee) / 256, blk>>>(
        gates, ob, oproj, tok_slot, tok_ns, out);
}

// round 17
// speedup vs baseline: 1.2304x; 1.2304x over previous
#include <cuda_runtime.h>
#include <math.h>
#include <stdint.h>

// Problem constants
#define Bb 2
#define Ss 1024
#define Ee 1024
#define NEx 8
#define Hh 16
#define Dh 64
#define NTOK (Bb*Ss)     // 2048
#define EH (Ee/2)        // 512
#define KT64 64          // K/16 for K=1024
#define NEB (NEx*Bb)     // 16

// ---------------- scratch (device globals) ----------------
__device__ __align__(16) float g_h [NTOK*EH];
__device__ __align__(16) float g_gates[NEx*NTOK];
__device__ __align__(16) float g_xpack [NTOK*Ee];        // packed+rounded x
__device__ __align__(16) float g_wpack [4*NEx*Ee*Ee];    // packed weights
__device__ __align__(16) float g_k [NEx*NTOK*Ee];        // per-expert K (tf32-rounded)
__device__ __align__(16) float g_v [NEx*NTOK*Ee];        // per-expert V (tf32-rounded)
__device__ __align__(16) float g_qc [NEB*Ss*Ee];         // compact Q*(1/8), tf32-rounded
__device__ __align__(16) float g_opack [NEB*Ss*Ee];      // packed gated attn out
__device__ __align__(16) float g_oproj [NEB*Ss*Ee];      // compact O-projection
__device__ int g_idx[NEB*Ss];
__device__ int g_cnt[NEB];
__device__ int g_tok_slot[NTOK*2];
__device__ int g_tok_ns[NTOK];

// ---------------- helpers ----------------
__device__ __forceinline__ uint32_t smem_u32(const void* p) {
    uint32_t a;
    asm("{ .reg .u64 t; cvta.to.shared.u64 t, %1; cvt.u32.u64 %0, t; }" : "=r"(a) : "l"(p));
    return a;
}
__device__ __forceinline__ float tf32r(float x) {
    uint32_t u;
    asm("cvt.rna.tf32.f32 %0, %1;" : "=r"(u) : "f"(x));
    return __uint_as_float(u);
}
#define CP_COMMIT() asm volatile("cp.async.commit_group;" ::: "memory")
#define CP_WAIT(n)  asm volatile("cp.async.wait_group %0;" :: "n"(n) : "memory")
#define CPA16(dst, src) \
    asm volatile("cp.async.cg.shared.global [%0], [%1], 16;" :: "r"(dst), "l"(src))

__device__ __forceinline__ void mma8(float* c, const uint32_t* a, const uint32_t* b) {
    asm volatile(
        "mma.sync.aligned.m16n8k8.row.col.f32.tf32.tf32.f32 "
        "{%0,%1,%2,%3}, {%4,%5,%6,%7}, {%8,%9}, {%0,%1,%2,%3};"
        : "+f"(c[0]), "+f"(c[1]), "+f"(c[2]), "+f"(c[3])
        : "r"(a[0]), "r"(a[1]), "r"(a[2]), "r"(a[3]), "r"(b[0]), "r"(b[1]));
}

// ============================================================
// Packing (tf32 RN + k-permute col' = (k%4)*4 + k/4)
// ============================================================
__global__ __launch_bounds__(256)
void pack_w_kernel(const float* __restrict__ qw, const float* __restrict__ kw,
                   const float* __restrict__ vw, const float* __restrict__ ow,
                   float* __restrict__ dst)
{
    const int kt = blockIdx.x, rb = blockIdx.y, m = blockIdx.z;
    const int tensor = m >> 3, e = m & 7;
    const float* src = (tensor == 0) ? qw : (tensor == 1) ? kw : (tensor == 2) ? vw : ow;
    src += (size_t)e * Ee * Ee + (size_t)rb * 128 * Ee + kt * 16;
    float* d = dst + (((size_t)m * 8 + rb) * KT64 + kt) * 2048;
    for (int el = threadIdx.x; el < 2048; el += 256) {
        int r = el >> 4, kk = el & 15;
        int colp = (kk & 3) * 4 + (kk >> 2);
        d[r * 16 + colp] = tf32r(src[(size_t)r * Ee + kk]);
    }
}

__global__ __launch_bounds__(256)
void pack_x_kernel(const float* __restrict__ x, float* __restrict__ dst)
{
    const int kt = blockIdx.x, mb = blockIdx.y;
    const float* src = x + (size_t)mb * 128 * Ee + kt * 16;
    float* d = dst + ((size_t)mb * KT64 + kt) * 2048;
    for (int el = threadIdx.x; el < 2048; el += 256) {
        int r = el >> 4, kk = el & 15;
        int colp = (kk & 3) * 4 + (kk >> 2);
        d[r * 16 + colp] = tf32r(src[(size_t)r * Ee + kk]);
    }
}

// ============================================================
// Batched tf32 mma.sync GEMM on packed operands. 4-stage pipeline.
// 128x128 CTA tile, 8 warps of 64x32, 2 CTA/SM.
// MODE 0: dense KV -> single tf32-rounded fp32 out. grid (8,16,16).
// MODE 1: Q compact, fused gather, scale*0.125, tf32 out. grid (8,8,16).
// MODE 2: O compact; A = packed flash output, fp32 out. grid (8,8,16).
// ============================================================
template<int MODE>
__global__ __launch_bounds__(256, 2)
void mma_gemm(const float* __restrict__ Apack, const float* __restrict__ Wpack,
              const float* __restrict__ bias0, const float* __restrict__ bias1,
              float* __restrict__ C0, float* __restrict__ C1,
              const int* __restrict__ idxp, const int* __restrict__ cnt)
{
    extern __shared__ __align__(16) float sm[];
    __shared__ int rmap[128];
    const int mb = blockIdx.y, nb = blockIdx.x, z = blockIdx.z;
    const int tid = threadIdx.x, lane = tid & 31, wid = tid >> 5;

    const float* Abase = nullptr;
    const float* Bbase;
    const float* bias = nullptr;
    float* Cp;
    if (MODE == 0) {
        const int e = z & 7, sel = z >> 3;
        Abase = Apack + (size_t)mb * KT64 * 2048;
        Bbase = Wpack + ((size_t)((1 + sel) * 8 + e) * 8 + nb) * KT64 * 2048;
        bias = (sel ? bias1 : bias0) + (size_t)e * Ee;
        Cp = (sel ? C1 : C0) + (size_t)e * NTOK * Ee;
    } else {
        const int e = z >> 1;
        const int cntv = cnt[z];
        if (mb * 128 >= cntv) return;
        if (MODE == 1) {
            const int b = z & 1;
            if (tid < 128) {
                int i = mb * 128 + tid;
                if (i > cntv - 1) i = cntv - 1;
                rmap[tid] = b * Ss + idxp[(size_t)z * Ss + i];
            }
        } else {
            Abase = Apack + ((size_t)z * 8 + mb) * KT64 * 2048;
        }
        Bbase = Wpack + ((size_t)((MODE == 1 ? 0 : 3) * 8 + e) * 8 + nb) * KT64 * 2048;
        if (MODE == 1) bias = bias0 + (size_t)e * Ee;
        Cp = C0 + (size_t)z * Ss * Ee;
    }
    if (MODE == 1) __syncthreads();

    const int g = lane >> 2, tg = lane & 3;
    const int warp_m = (wid & 1) * 64, warp_n = (wid >> 1) * 32;
    const uint32_t sa = smem_u32(sm);

    float acc[4][4][4];
#pragma unroll
    for (int mt = 0; mt < 4; mt++)
#pragma unroll
        for (int nt = 0; nt < 4; nt++)
#pragma unroll
            for (int r = 0; r < 4; r++) acc[mt][nt][r] = 0.f;

    auto load_stage = [&](int st, int kt) {
        const uint32_t db = sa + (uint32_t)st * 16384u;
#pragma unroll
        for (int l = 0; l < 2; l++) {
            int c = tid + l * 256;
            const float* ga;
            if (MODE == 1) {
                int row = c >> 2, q = c & 3;
                int t = rmap[row];
                ga = Apack + ((size_t)(t >> 7) * KT64 + kt) * 2048 + (t & 127) * 16 + q * 4;
            } else {
                ga = Abase + (size_t)kt * 2048 + c * 4;
            }
            CPA16(db + c * 16, ga);
            CPA16(db + 8192 + c * 16, Bbase + (size_t)kt * 2048 + c * 4);
        }
        CP_COMMIT();
    };

    load_stage(0, 0);
    load_stage(1, 1);
    load_stage(2, 2);

    for (int kt = 0; kt < KT64; kt++) {
        CP_WAIT(2);            // group kt complete
        __syncthreads();       // also orders reuse of the stage refilled below
        int lkt = kt + 3; if (lkt > KT64 - 1) lkt = KT64 - 1;
        load_stage((kt + 3) & 3, lkt);   // uniform prefetch (clamped)

        const uint4* As = (const uint4*)(sm + (kt & 3) * 4096);
        const uint4* Bs = As + 512;

        uint4 aL[4], aH[4], bb[4];
#pragma unroll
        for (int mt = 0; mt < 4; mt++) {
            const int r0 = warp_m + mt * 16 + g;
            aL[mt] = As[r0 * 4 + tg];
            aH[mt] = As[(r0 + 8) * 4 + tg];
        }
#pragma unroll
        for (int nt = 0; nt < 4; nt++)
            bb[nt] = Bs[(warp_n + nt * 8 + g) * 4 + tg];

#pragma unroll
        for (int mt = 0; mt < 4; mt++)
#pragma unroll
            for (int nt = 0; nt < 4; nt++) {
                uint32_t a[4] = {aL[mt].x, aH[mt].x, aL[mt].y, aH[mt].y};
                uint32_t b[2] = {bb[nt].x, bb[nt].y};
                mma8(acc[mt][nt], a, b);
            }
#pragma unroll
        for (int mt = 0; mt < 4; mt++)
#pragma unroll
            for (int nt = 0; nt < 4; nt++) {
                uint32_t a[4] = {aL[mt].z, aH[mt].z, aL[mt].w, aH[mt].w};
                uint32_t b[2] = {bb[nt].z, bb[nt].w};
                mma8(acc[mt][nt], a, b);
            }
    }

    // epilogue
    const int n0 = nb * 128;
#pragma unroll
    for (int mt = 0; mt < 4; mt++) {
#pragma unroll
        for (int h2 = 0; h2 < 2; h2++) {
            const int ti = mb * 128 + warp_m + mt * 16 + g + h2 * 8;
            float* crp = Cp + (size_t)ti * Ee + n0;
#pragma unroll
            for (int nt = 0; nt < 4; nt++) {
                const int col = warp_n + nt * 8 + 2 * tg;
                float v0 = acc[mt][nt][h2 * 2 + 0];
                float v1 = acc[mt][nt][h2 * 2 + 1];
                if (MODE != 2) {
                    v0 += bias[n0 + col];
                    v1 += bias[n0 + col + 1];
                }
                if (MODE == 0) {
                    *(float2*)(crp + col) = make_float2(tf32r(v0), tf32r(v1));
                } else if (MODE == 1) {
                    *(float2*)(crp + col) =
                        make_float2(tf32r(v0 * 0.125f), tf32r(v1 * 0.125f));
                } else {
                    *(float2*)(crp + col) = make_float2(v0, v1);
                }
            }
        }
    }
}

// ============================================================
// fp32 SGEMM (router only): C = A @ B^T + bias
// ============================================================
__global__ __launch_bounds__(256)
void gemm_nt_kernel(const float* __restrict__ A, const float* __restrict__ Bm,
                    const float* __restrict__ bias, float* __restrict__ C,
                    int M, int N, int K)
{
    __shared__ __align__(16) float As[2][16][132];
    __shared__ __align__(16) float Bs[2][16][132];
    const int m0 = blockIdx.y * 128, n0 = blockIdx.x * 128;
    const int tid = threadIdx.x;
    const int tx = tid & 15, ty = tid >> 4;
    const int lrow = tid >> 2, lq = tid & 3;
    const float* Ab = A + (size_t)m0 * K + lq * 4;
    const float* Bb2 = Bm + (size_t)n0 * K + lq * 4;
    float acc[8][8];
#pragma unroll
    for (int i = 0; i < 8; i++)
#pragma unroll
        for (int j = 0; j < 8; j++) acc[i][j] = 0.f;
    const int KTl = K >> 4;
#pragma unroll
    for (int i = 0; i < 2; i++) {
        int row = lrow + i * 64;
        float4 va = *(const float4*)(Ab + (size_t)row * K);
        float4 vb = *(const float4*)(Bb2 + (size_t)row * K);
        As[0][lq*4+0][row] = va.x; As[0][lq*4+1][row] = va.y;
        As[0][lq*4+2][row] = va.z; As[0][lq*4+3][row] = va.w;
        Bs[0][lq*4+0][row] = vb.x; Bs[0][lq*4+1][row] = vb.y;
        Bs[0][lq*4+2][row] = vb.z; Bs[0][lq*4+3][row] = vb.w;
    }
    __syncthreads();
    for (int kt = 0; kt < KTl; kt++) {
        const int cb = kt & 1, nbuf = cb ^ 1;
        float4 pa[2], pb[2];
        if (kt + 1 < KTl) {
#pragma unroll
            for (int i = 0; i < 2; i++) {
                int row = lrow + i * 64;
                pa[i] = *(const float4*)(Ab + (size_t)row * K + (kt + 1) * 16);
                pb[i] = *(const float4*)(Bb2 + (size_t)row * K + (kt + 1) * 16);
            }
        }
#pragma unroll
        for (int kk = 0; kk < 16; kk++) {
            float a[8], bv[8];
            *(float4*)&a[0] = *(const float4*)&As[cb][kk][ty * 8];
            *(float4*)&a[4] = *(const float4*)&As[cb][kk][ty * 8 + 4];
            *(float4*)&bv[0] = *(const float4*)&Bs[cb][kk][tx * 8];
            *(float4*)&bv[4] = *(const float4*)&Bs[cb][kk][tx * 8 + 4];
#pragma unroll
            for (int i = 0; i < 8; i++)
#pragma unroll
                for (int j = 0; j < 8; j++)
                    acc[i][j] = fmaf(a[i], bv[j], acc[i][j]);
        }
        if (kt + 1 < KTl) {
#pragma unroll
            for (int i = 0; i < 2; i++) {
                int row = lrow + i * 64;
                As[nbuf][lq*4+0][row] = pa[i].x; As[nbuf][lq*4+1][row] = pa[i].y;
                As[nbuf][lq*4+2][row] = pa[i].z; As[nbuf][lq*4+3][row] = pa[i].w;
                Bs[nbuf][lq*4+0][row] = pb[i].x; Bs[nbuf][lq*4+1][row] = pb[i].y;
                Bs[nbuf][lq*4+2][row] = pb[i].z; Bs[nbuf][lq*4+3][row] = pb[i].w;
            }
        }
        __syncthreads();
    }
#pragma unroll
    for (int i = 0; i < 8; i++) {
        int m = m0 + ty * 8 + i;
        float* Crow = C + (size_t)m * N + n0 + tx * 8;
#pragma unroll
        for (int j = 0; j < 8; j++) {
            float v = acc[i][j];
            v += bias[n0 + tx * 8 + j];
            Crow[j] = v;
        }
    }
}

// ============================================================
// Fused LayerNorm + ReLU + router logits + softmax + top-2 gates.
// ============================================================
__global__ __launch_bounds__(256)
void ln_router_kernel(const float* __restrict__ h, const float* __restrict__ g,
                      const float* __restrict__ b, const float* __restrict__ rW2,
                      const float* __restrict__ rb2, float* __restrict__ gates)
{
    const int t = blockIdx.x;
    __shared__ float hs[EH];
    __shared__ float red[16];
    __shared__ float sh_mean, sh_rstd;
    __shared__ float lg[NEx];
    const float* row = h + (size_t)t * EH;
    const int lane = threadIdx.x & 31, w = threadIdx.x >> 5;

    float s = 0.f, s2 = 0.f;
    for (int i = threadIdx.x; i < EH; i += 256) {
        float v = row[i];
        hs[i] = v;
        s += v;
        s2 = fmaf(v, v, s2);
    }
#pragma unroll
    for (int o = 16; o; o >>= 1) {
        s  += __shfl_xor_sync(0xffffffffu, s, o);
        s2 += __shfl_xor_sync(0xffffffffu, s2, o);
    }
    if (lane == 0) { red[w] = s; red[8 + w] = s2; }
    __syncthreads();
    if (threadIdx.x == 0) {
        float ts = 0.f, ts2 = 0.f;
        for (int i = 0; i < 8; i++) { ts += red[i]; ts2 += red[8 + i]; }
        float mean = ts * (1.f / EH);
        float var = ts2 * (1.f / EH) - mean * mean;
        sh_mean = mean;
        sh_rstd = rsqrtf(var + 1e-5f);
    }
    __syncthreads();
    const float mean = sh_mean, rstd = sh_rstd;
    for (int i = threadIdx.x; i < EH; i += 256) {
        float v = (hs[i] - mean) * rstd * g[i] + b[i];
        hs[i] = fmaxf(v, 0.f);
    }
    __syncthreads();

    float sdot = 0.f;
    const float* wrow = rW2 + (size_t)w * EH;
    for (int i = lane; i < EH; i += 32) sdot = fmaf(hs[i], wrow[i], sdot);
#pragma unroll
    for (int o = 16; o; o >>= 1) sdot += __shfl_xor_sync(0xffffffffu, sdot, o);
    if (lane == 0) lg[w] = sdot + rb2[w];
    __syncthreads();
    if (threadIdx.x == 0) {
        float mx = lg[0];
        for (int e = 1; e < NEx; e++) mx = fmaxf(mx, lg[e]);
        float pe[NEx]; float sum = 0.f;
        for (int e = 0; e < NEx; e++) { pe[e] = expf(lg[e] - mx); sum += pe[e]; }
        float inv = 1.f / sum;
        for (int e = 0; e < NEx; e++) pe[e] *= inv;
        int i1 = 0;
        for (int e = 1; e < NEx; e++) if (pe[e] > pe[i1]) i1 = e;
        int i2 = (i1 == 0) ? 1 : 0;
        for (int e = 0; e < NEx; e++) {
            if (e == i1) continue;
            if (pe[e] > pe[i2]) i2 = e;
        }
        float tsum = pe[i1] + pe[i2];
        for (int e = 0; e < NEx; e++) gates[e * NTOK + t] = 0.f;
        gates[i1 * NTOK + t] = pe[i1] / tsum;
        gates[i2 * NTOK + t] = pe[i2] / tsum;
    }
}

// ============================================================
// lists + slots
// ============================================================
__global__ __launch_bounds__(256)
void zero_meta_kernel(int* __restrict__ cnt, int* __restrict__ tok_ns)
{
    const int i = blockIdx.x * 256 + threadIdx.x;
    if (i < NEB) cnt[i] = 0;
    if (i < NTOK) tok_ns[i] = 0;
}
__global__ __launch_bounds__(256)
void build_lists_kernel(const float* __restrict__ gates, int* __restrict__ idx,
                        int* __restrict__ cnt, int* __restrict__ tok_slot,
                        int* __restrict__ tok_ns)
{
    const int e = blockIdx.x;
    for (int t = threadIdx.x; t < NTOK; t += 256) {
        if (gates[e * NTOK + t] > 0.f) {
            int b = t >> 10, s = t & (Ss - 1);
            int pos = atomicAdd(&cnt[e * Bb + b], 1);
            idx[(e * Bb + b) * Ss + pos] = s;
            int sl = atomicAdd(&tok_ns[t], 1);
            if (sl < 2) tok_slot[t * 2 + sl] = (e * Bb + b) * Ss + pos;
        }
    }
}

// ============================================================
// Tensor-core flash attention, single-rounded tf32 operands.
// QK^T: 1-term (q x k, both pre-rounded; Q pre-scaled by 1/8).
// PV: 1-term (p_hi x v).  106.5 KB smem -> 2 CTAs/SM.
// smem: Ks[2][64][68], Vs[2][64][72], Ps[128][68] (all float).
// ============================================================
__global__ __launch_bounds__(256, 2)
void flash_attn_tensor(const float* __restrict__ Qf, const float* __restrict__ Kf,
                       const float* __restrict__ Vf, const float* __restrict__ gates,
                       const int* __restrict__ idx, const int* __restrict__ cnt,
                       float* __restrict__ Opack)
{
    extern __shared__ __align__(16) char smc[];
    // layout: Ks 2x17408 B @0, Vs 2x18432 B @34816, Ps @71680
    float (*Ps)[68] = (float(*)[68])(smc + 71680);
    __shared__ float sgate[128];
    __shared__ int s_nact;

    const int bx = blockIdx.x;
    const int z = blockIdx.y >> 4, hh = blockIdx.y & 15;
    const int e = z >> 1, b = z & 1;
    const int tid = threadIdx.x, lane = tid & 31, wid = tid >> 5;
    const int g = lane >> 2, tg = lane & 3;
    const int row0 = wid * 16;

    if (tid == 0) s_nact = cnt[z];
    __syncthreads();
    const int n_act = s_nact;
    if (bx * 128 >= n_act) return;

    const size_t kbase = ((size_t)e * NTOK + (size_t)b * Ss) * Ee + (size_t)hh * Dh;
    const uint32_t sa = smem_u32(smc);

    auto load_kv = [&](int buf, int nt) {
        const float* kg = Kf + kbase + (size_t)(nt * 64) * Ee;
        const float* vg = Vf + kbase + (size_t)(nt * 64) * Ee;
        const uint32_t kb2 = sa + (uint32_t)buf * 17408u;
        const uint32_t vb2 = sa + 34816u + (uint32_t)buf * 18432u;
#pragma unroll
        for (int l = 0; l < 4; l++) {
            int i = tid + l * 256;
            int r = i >> 4, c4 = i & 15;
            CPA16(kb2 + (r * 68 + c4 * 4) * 4, kg + (size_t)r * Ee + c4 * 4);
            CPA16(vb2 + (r * 72 + c4 * 4) * 4, vg + (size_t)r * Ee + c4 * 4);
        }
        CP_COMMIT();
    };

    load_kv(0, 0);   // prefetch first tile ASAP

    if (tid < 128) {
        int i = bx * 128 + tid;
        sgate[tid] = (i < n_act)
            ? gates[e * NTOK + b * Ss + idx[(size_t)z * Ss + i]] : 1.f;
    }

    // Q fragments (pre-scaled/rounded) direct from global
    uint32_t qh[8][4];
    {
        const float* qp = Qf + ((size_t)z * Ss + bx * 128) * Ee + (size_t)hh * Dh;
#pragma unroll
        for (int kc = 0; kc < 8; kc++) {
#pragma unroll
            for (int j = 0; j < 4; j++) {
                const int qrow = row0 + g + (j & 1) * 8;
                const int col = kc * 8 + tg + (j >> 1) * 4;
                qh[kc][j] = __float_as_uint(qp[(size_t)qrow * Ee + col]);
            }
        }
    }

    float oacc[8][4];
#pragma unroll
    for (int d8 = 0; d8 < 8; d8++)
#pragma unroll
        for (int r = 0; r < 4; r++) oacc[d8][r] = 0.f;
    float m0 = -INFINITY, m1 = -INFINITY, l0 = 0.f, l1 = 0.f;

    for (int nt = 0; nt < Ss / 64; nt++) {
        const int buf = nt & 1;
        if (nt + 1 < Ss / 64) { load_kv(buf ^ 1, nt + 1); CP_WAIT(1); }
        else CP_WAIT(0);
        __syncthreads();

        float (*Ks)[68] = (float(*)[68])(smc + buf * 17408);
        float (*Vs)[72] = (float(*)[72])(smc + 34816 + buf * 18432);

        // ---- S = Q K^T (1-term) ----
        float sacc[8][4];
#pragma unroll
        for (int n8 = 0; n8 < 8; n8++)
#pragma unroll
            for (int r = 0; r < 4; r++) sacc[n8][r] = 0.f;

#pragma unroll
        for (int kc = 0; kc < 8; kc++) {
#pragma unroll
            for (int n8 = 0; n8 < 8; n8++) {
                uint32_t kh2[2];
                kh2[0] = __float_as_uint(Ks[n8 * 8 + g][kc * 8 + tg]);
                kh2[1] = __float_as_uint(Ks[n8 * 8 + g][kc * 8 + tg + 4]);
                mma8(sacc[n8], qh[kc], kh2);
            }
        }

        // ---- online softmax (fp32) ----
        float rmax0 = -INFINITY, rmax1 = -INFINITY;
#pragma unroll
        for (int n8 = 0; n8 < 8; n8++) {
            rmax0 = fmaxf(rmax0, fmaxf(sacc[n8][0], sacc[n8][1]));
            rmax1 = fmaxf(rmax1, fmaxf(sacc[n8][2], sacc[n8][3]));
        }
        rmax0 = fmaxf(rmax0, __shfl_xor_sync(0xffffffffu, rmax0, 1));
        rmax0 = fmaxf(rmax0, __shfl_xor_sync(0xffffffffu, rmax0, 2));
        rmax1 = fmaxf(rmax1, __shfl_xor_sync(0xffffffffu, rmax1, 1));
        rmax1 = fmaxf(rmax1, __shfl_xor_sync(0xffffffffu, rmax1, 2));
        float newm0 = fmaxf(m0, rmax0), newm1 = fmaxf(m1, rmax1);
        float corr0 = __expf(m0 - newm0), corr1 = __expf(m1 - newm1);
        float rs0 = 0.f, rs1 = 0.f;
#pragma unroll
        for (int n8 = 0; n8 < 8; n8++) {
            float p0 = __expf(sacc[n8][0] - newm0);
            float p1 = __expf(sacc[n8][1] - newm0);
            float p2 = __expf(sacc[n8][2] - newm1);
            float p3 = __expf(sacc[n8][3] - newm1);
            rs0 += p0 + p1; rs1 += p2 + p3;
            *(float2*)&Ps[row0 + g][n8 * 8 + 2 * tg] = make_float2(p0, p1);
            *(float2*)&Ps[row0 + g + 8][n8 * 8 + 2 * tg] = make_float2(p2, p3);
        }
        rs0 += __shfl_xor_sync(0xffffffffu, rs0, 1);
        rs0 += __shfl_xor_sync(0xffffffffu, rs0, 2);
        rs1 += __shfl_xor_sync(0xffffffffu, rs1, 1);
        rs1 += __shfl_xor_sync(0xffffffffu, rs1, 2);
        l0 = l0 * corr0 + rs0; m0 = newm0;
        l1 = l1 * corr1 + rs1; m1 = newm1;
#pragma unroll
        for (int d8 = 0; d8 < 8; d8++) {
            oacc[d8][0] *= corr0; oacc[d8][1] *= corr0;
            oacc[d8][2] *= corr1; oacc[d8][3] *= corr1;
        }
        __syncwarp();  // P rows are warp-private

        // ---- O += P V (1-term: P_hi x V) ----
#pragma unroll
        for (int kc = 0; kc < 8; kc++) {
            uint32_t ph[4];
#pragma unroll
            for (int j = 0; j < 4; j++) {
                float v = Ps[row0 + g + (j & 1) * 8][kc * 8 + tg + (j >> 1) * 4];
                ph[j] = __float_as_uint(tf32r(v));
            }
#pragma unroll
            for (int d8 = 0; d8 < 8; d8++) {
                uint32_t vh2[2];
                vh2[0] = __float_as_uint(Vs[kc * 8 + tg][d8 * 8 + g]);
                vh2[1] = __float_as_uint(Vs[kc * 8 + tg + 4][d8 * 8 + g]);
                mma8(oacc[d8], ph, vh2);
            }
        }
        __syncthreads();  // this tile's buffers safe to refill next iter
    }

    // ---- epilogue: /l, *gate, write PACKED (fused pack_o) ----
    float* dbase = Opack + ((size_t)(z * 8 + bx) * KT64) * 2048;
#pragma unroll
    for (int half = 0; half < 2; half++) {
        const int rr = row0 + g + half * 8;
        const int rg = bx * 128 + rr;
        if (rg < n_act) {
            const float gv = sgate[rr] / (half ? l1 : l0);
            float* dp = dbase + rr * 16;
#pragma unroll
            for (int d8 = 0; d8 < 8; d8++) {
#pragma unroll
                for (int w2 = 0; w2 < 2; w2++) {
                    const int c = hh * 64 + d8 * 8 + 2 * tg + w2;
                    const int kt = c >> 4, kk = c & 15;
                    const int colp = (kk & 3) * 4 + (kk >> 2);
                    const float val = oacc[d8][half * 2 + w2] * gv;
                    dp[(size_t)kt * 2048 + colp] = tf32r(val);
                }
            }
        }
    }
}

// ============================================================
// combine: out = Sum_e gates*ob + Sum over token's <=2 compact rows
// ============================================================
__global__ __launch_bounds__(256)
void combine_kernel(const float* __restrict__ gates, const float* __restrict__ ob,
                    const float* __restrict__ oproj, const int* __restrict__ tok_slot,
                    const int* __restrict__ tok_ns, float* __restrict__ out)
{
    const int i = blockIdx.x * 256 + threadIdx.x;
    const int t = i >> 10;
    const int j = i & (Ee - 1);
    float s = 0.f;
#pragma unroll
    for (int e = 0; e < NEx; e++)
        s = fmaf(gates[e * NTOK + t], ob[e * Ee + j], s);
    const int ns = tok_ns[t];
    int s0 = tok_slot[t * 2], s1 = tok_slot[t * 2 + 1];
    if (ns >= 2) {
        if (s1 < s0) { int tmp = s0; s0 = s1; s1 = tmp; }
        s += oproj[(size_t)s0 * Ee + j];
        s += oproj[(size_t)s1 * Ee + j];
    } else if (ns == 1) {
        s += oproj[(size_t)s0 * Ee + j];
    }
    out[i] = s;
}

// ============================================================
// launch
// ============================================================
extern "C" void kernel_launch(void* const* d_in, const int* in_sizes, int n_in,
                              void* d_out, int out_size)
{
    const float* x    = (const float*)d_in[0];
    const float* rW1  = (const float*)d_in[1];
    const float* rb1  = (const float*)d_in[2];
    const float* ln_g = (const float*)d_in[3];
    const float* ln_b = (const float*)d_in[4];
    const float* rW2  = (const float*)d_in[5];
    const float* rb2  = (const float*)d_in[6];
    const float* qW   = (const float*)d_in[7];
    const float* qb   = (const float*)d_in[8];
    const float* kW   = (const float*)d_in[9];
    const float* kb   = (const float*)d_in[10];
    const float* vW   = (const float*)d_in[11];
    const float* vb   = (const float*)d_in[12];
    const float* oW   = (const float*)d_in[13];
    const float* ob   = (const float*)d_in[14];
    float* out = (float*)d_out;

    float *h, *gates, *xpack, *wpack, *k, *v, *qc, *opack, *oproj;
    int *idx, *cnt, *tok_slot, *tok_ns;
    cudaGetSymbolAddress((void**)&h, g_h);
    cudaGetSymbolAddress((void**)&gates, g_gates);
    cudaGetSymbolAddress((void**)&xpack, g_xpack);
    cudaGetSymbolAddress((void**)&wpack, g_wpack);
    cudaGetSymbolAddress((void**)&k, g_k);
    cudaGetSymbolAddress((void**)&v, g_v);
    cudaGetSymbolAddress((void**)&qc, g_qc);
    cudaGetSymbolAddress((void**)&opack, g_opack);
    cudaGetSymbolAddress((void**)&oproj, g_oproj);
    cudaGetSymbolAddress((void**)&idx, g_idx);
    cudaGetSymbolAddress((void**)&cnt, g_cnt);
    cudaGetSymbolAddress((void**)&tok_slot, g_tok_slot);
    cudaGetSymbolAddress((void**)&tok_ns, g_tok_ns);

    constexpr int FLASH_SMEM = 2 * 17408 + 2 * 18432 + 128 * 68 * 4;  // 106,496 B
    constexpr int GEMM_SMEM = 4 * 16384;                              // 65,536 B
    cudaFuncSetAttribute(flash_attn_tensor,
                         cudaFuncAttributeMaxDynamicSharedMemorySize, FLASH_SMEM);
    cudaFuncSetAttribute(mma_gemm<0>,
                         cudaFuncAttributeMaxDynamicSharedMemorySize, GEMM_SMEM);
    cudaFuncSetAttribute(mma_gemm<1>,
                         cudaFuncAttributeMaxDynamicSharedMemorySize, GEMM_SMEM);
    cudaFuncSetAttribute(mma_gemm<2>,
                         cudaFuncAttributeMaxDynamicSharedMemorySize, GEMM_SMEM);

    const dim3 blk(256);

    // 1-2: pack weights and x
    pack_w_kernel<<<dim3(64, 8, 32), blk>>>(qW, kW, vW, oW, wpack);
    pack_x_kernel<<<dim3(64, 16), blk>>>(x, xpack);
    // 3: router hidden (fp32)
    gemm_nt_kernel<<<dim3(EH / 128, NTOK / 128), blk>>>(x, rW1, rb1, h, NTOK, EH, Ee);
    // 4: K+V projections, all experts, single-rounded output (PROFILED LAUNCH)
    mma_gemm<0><<<dim3(8, 16, 16), blk, GEMM_SMEM>>>(
        xpack, wpack, kb, vb, k, v, nullptr, nullptr);
    // 5-7: fused LN+router, lists
    ln_router_kernel<<<NTOK, blk>>>(h, ln_g, ln_b, rW2, rb2, gates);
    zero_meta_kernel<<<NTOK / 256, blk>>>(cnt, tok_ns);
    build_lists_kernel<<<NEx, blk>>>(gates, idx, cnt, tok_slot, tok_ns);
    // 8: Q projections, fused gather, scaled single-tf32 output
    mma_gemm<1><<<dim3(8, 8, NEB), blk, GEMM_SMEM>>>(
        xpack, wpack, qb, nullptr, qc, nullptr, idx, cnt);
    // 9: flash attention (1-term QK / 1-term PV, 2 CTAs/SM)
    flash_attn_tensor<<<dim3(8, NEB * Hh), blk, FLASH_SMEM>>>(
        qc, k, v, gates, idx, cnt, opack);
    // 10: O projections on packed flash output
    mma_gemm<2><<<dim3(8, 8, NEB), blk, GEMM_SMEM>>>(
        opack, wpack, nullptr, nullptr, oproj, nullptr, nullptr, cnt);
    // 11: combine
    combine_kernel<<<(NTOK * Ee) / 256, blk>>>(
        gates, ob, oproj, tok_slot, tok_ns, out);
}